// round 14
// baseline (speedup 1.0000x reference)
#include <cuda_runtime.h>
#include <cuda_bf16.h>
#include <cuda_fp16.h>
#include <stdint.h>
#include <math.h>

#define BATCH   8
#define SEQ     4096
#define DIMN    512
#define HEADS   8
#define DHEAD   64
#define WIN     128
#define NW      (SEQ / WIN)
#define NTOK    (BATCH * SEQ)
#define QKVD    (3 * DIMN)
#define FFD     (4 * DIMN)

#define WSCALE     512.0f            // weights pre-scaled by 512 (exact pow2)
#define WSCALE_INV (1.0f / 512.0f)

// ======================= scratch (static device memory) ========================
__device__ float  g_qkv [(size_t)NTOK * QKVD];
__device__ float  g_x1  [(size_t)NTOK * DIMN];
__device__ __half g_h   [(size_t)NTOK * DIMN];
__device__ __half g_at  [(size_t)NTOK * DIMN];
__device__ __half g_f1  [(size_t)NTOK * FFD];
__device__ __half g_wqkv[QKVD * DIMN];
__device__ __half g_wout[DIMN * DIMN];
__device__ __half g_wff1[FFD * DIMN];
__device__ __half g_wff2[DIMN * FFD];
__device__ float  g_rotc[SEQ * 32];   // rotary cos table [pos][lane]
__device__ float  g_rots[SEQ * 32];   // rotary sin table

// ============================ helpers ==========================================
__device__ __forceinline__ uint32_t smem_u32(const void* p) {
    uint32_t a;
    asm("{ .reg .u64 t; cvta.to.shared.u64 t, %1; cvt.u32.u64 %0, t; }" : "=r"(a) : "l"(p));
    return a;
}
#define SWZ(o) ((o) ^ (((o) >> 3) & 0x70))   // SW128 swizzle, 128B rows

__device__ __forceinline__ void cp_async16(uint32_t dst, const void* src) {
    asm volatile("cp.async.cg.shared.global [%0], [%1], 16;" :: "r"(dst), "l"(src));
}
__device__ __forceinline__ void cp_commit() {
    asm volatile("cp.async.commit_group;");
}
template <int N>
__device__ __forceinline__ void cp_wait() {
    asm volatile("cp.async.wait_group %0;" :: "n"(N));
}
__device__ __forceinline__ void ldmatrix_x4(uint32_t& r0, uint32_t& r1,
                                            uint32_t& r2, uint32_t& r3, uint32_t a) {
    asm volatile("ldmatrix.sync.aligned.m8n8.x4.shared.b16 {%0,%1,%2,%3}, [%4];"
                 : "=r"(r0), "=r"(r1), "=r"(r2), "=r"(r3) : "r"(a));
}
__device__ __forceinline__ void mma_fp16(float* c, const uint32_t* a, const uint32_t* b) {
    asm volatile("mma.sync.aligned.m16n8k16.row.col.f32.f16.f16.f32 "
                 "{%0,%1,%2,%3}, {%4,%5,%6,%7}, {%8,%9}, {%0,%1,%2,%3};"
                 : "+f"(c[0]), "+f"(c[1]), "+f"(c[2]), "+f"(c[3])
                 : "r"(a[0]), "r"(a[1]), "r"(a[2]), "r"(a[3]), "r"(b[0]), "r"(b[1]));
}

// ---- packed fp32x2 (Blackwell): 2 IEEE fp32 ops per instruction ----
__device__ __forceinline__ unsigned long long ffma2(unsigned long long a,
                                                    unsigned long long b,
                                                    unsigned long long c) {
    unsigned long long d;
    asm("fma.rn.f32x2 %0, %1, %2, %3;" : "=l"(d) : "l"(a), "l"(b), "l"(c));
    return d;
}
__device__ __forceinline__ unsigned long long addf2(unsigned long long a,
                                                    unsigned long long b) {
    unsigned long long d;
    asm("add.rn.f32x2 %0, %1, %2;" : "=l"(d) : "l"(a), "l"(b));
    return d;
}
__device__ __forceinline__ float2 unpack2(unsigned long long v) {
    float2 r;
    asm("mov.b64 {%0, %1}, %2;" : "=f"(r.x), "=f"(r.y) : "l"(v));
    return r;
}
__device__ __forceinline__ unsigned long long pack2(float x, float y) {
    unsigned long long v;
    asm("mov.b64 %0, {%1, %2};" : "=l"(v) : "f"(x), "f"(y));
    return v;
}

// ================= LayerNorm -> fp16. block = token =============================
__global__ __launch_bounds__(128) void ln_kernel(const float* __restrict__ in,
                                                 const float* __restrict__ gamma,
                                                 const float* __restrict__ beta,
                                                 __half* __restrict__ oh)
{
    int t = blockIdx.x;
    int tid = threadIdx.x;
    const float4* row = (const float4*)(in + (size_t)t * DIMN);
    float4 v = row[tid];
    float s  = v.x + v.y + v.z + v.w;
    float ss = v.x * v.x + v.y * v.y + v.z * v.z + v.w * v.w;
#pragma unroll
    for (int o = 16; o > 0; o >>= 1) {
        s  += __shfl_xor_sync(0xffffffffu, s, o);
        ss += __shfl_xor_sync(0xffffffffu, ss, o);
    }
    __shared__ float sm[4], sm2[4];
    int w = tid >> 5, lane = tid & 31;
    if (lane == 0) { sm[w] = s; sm2[w] = ss; }
    __syncthreads();
    s  = sm[0] + sm[1] + sm[2] + sm[3];
    ss = sm2[0] + sm2[1] + sm2[2] + sm2[3];
    float mean = s * (1.0f / DIMN);
    float var  = ss * (1.0f / DIMN) - mean * mean;
    float inv  = rsqrtf(var + 1e-5f);
    float4 g = ((const float4*)gamma)[tid];
    float4 b = ((const float4*)beta)[tid];
    float o0 = (v.x - mean) * inv * g.x + b.x;
    float o1 = (v.y - mean) * inv * g.y + b.y;
    float o2 = (v.z - mean) * inv * g.z + b.z;
    float o3 = (v.w - mean) * inv * g.w + b.w;
    __half2 p0 = __floats2half2_rn(o0, o1);
    __half2 p1 = __floats2half2_rn(o2, o3);
    *(uint2*)(oh + (size_t)t * DIMN + tid * 4) = make_uint2(*(uint32_t*)&p0, *(uint32_t*)&p1);
}

// ========= weight convert: fp32 -> fp16 of (512 * w) ============================
__global__ void wconv_kernel(const float* __restrict__ in,
                             __half* __restrict__ oh, int n4)
{
    int i = blockIdx.x * blockDim.x + threadIdx.x;
    if (i >= n4) return;
    float4 v = ((const float4*)in)[i];
    __half2 p0 = __floats2half2_rn(v.x * WSCALE, v.y * WSCALE);
    __half2 p1 = __floats2half2_rn(v.z * WSCALE, v.w * WSCALE);
    ((uint2*)oh)[i] = make_uint2(*(uint32_t*)&p0, *(uint32_t*)&p1);
}

// ========= rotary table: cos/sin of fp32 phase, exact double trig ===============
__global__ void rotary_kernel(float* __restrict__ rc, float* __restrict__ rs)
{
    int idx = blockIdx.x * blockDim.x + threadIdx.x;   // SEQ*32
    int n = idx >> 5, lane = idx & 31;
    double invf_d = exp(-(double)(2 * lane) * (9.210340371976184 / 64.0));
    float ph = (float)n * (float)invf_d;               // fp32 phase (matches ref)
    double sd, cd;
    sincos((double)ph, &sd, &cd);
    rc[idx] = (float)cd;
    rs[idx] = (float)sd;
}

// ====== local-window attention with FUSED l2norm+scale+rotary ==================
// Reads raw qkv (GEMM0 output). Q transformed in registers per thread; K rows
// transformed in smem after the raw load (2 threads/row, partial ssq combined
// with one shfl). Fixed-offset softmax + packed f32x2 math as in R13.
__global__ __launch_bounds__(128) void attn_kernel(const float* __restrict__ qkv,
                                                   const float* __restrict__ qsc,
                                                   const float* __restrict__ ksc,
                                                   const float* __restrict__ rc,
                                                   const float* __restrict__ rs,
                                                   __half* __restrict__ oh)
{
    __shared__ float sK[64][DHEAD];
    __shared__ float sV[64][DHEAD];
    __shared__ float sQsc[64], sKsc[64];

    int w = blockIdx.x, h = blockIdx.y, b = blockIdx.z;
    int i = threadIdx.x;
    int tok0 = b * SEQ + w * WIN;
    int tok  = tok0 + i;

    if (i < 64) sQsc[i] = qsc[i];
    else        sKsc[i - 64] = ksc[i - 64];
    __syncthreads();

    // ---- Q: load raw, l2norm*scale + rotary in registers, pack to f32x2 ----
    unsigned long long q2[32];
    {
        float qv[64];
        const float4* srcQ = (const float4*)(qkv + (size_t)tok * QKVD + h * DHEAD);
#pragma unroll
        for (int d4 = 0; d4 < 16; ++d4) {
            float4 t4 = srcQ[d4];
            qv[d4 * 4 + 0] = t4.x; qv[d4 * 4 + 1] = t4.y;
            qv[d4 * 4 + 2] = t4.z; qv[d4 * 4 + 3] = t4.w;
        }
        float ssq = 0.f;
#pragma unroll
        for (int d = 0; d < 64; ++d) ssq += qv[d] * qv[d];
        float inv = 1.0f / fmaxf(sqrtf(ssq), 1e-12f);
        int n = tok & (SEQ - 1);
        const float* rcn = rc + n * 32;
        const float* rsn = rs + n * 32;
#pragma unroll
        for (int d = 0; d < 32; ++d) {
            float a = qv[d] * inv * sQsc[d];
            float bb = qv[d + 32] * inv * sQsc[d + 32];
            float c_ = rcn[d], s_ = rsn[d];
            qv[d]      = a * c_ - bb * s_;
            qv[d + 32] = bb * c_ + a * s_;
        }
#pragma unroll
        for (int j = 0; j < 32; ++j) q2[j] = pack2(qv[2 * j], qv[2 * j + 1]);
    }

    unsigned long long acc2[32];
#pragma unroll
    for (int d = 0; d < 32; ++d) acc2[d] = 0ull;
    float l = 0.f;

#pragma unroll 1
    for (int c = 0; c < 4; ++c) {
        if (c < 2 && w == 0) continue;

        __syncthreads();
        {
            int r  = i >> 1;
            int f0 = (i & 1) * 8;
            int ktok = tok0 + c * 64 - WIN + r;
            const float4* sk = (const float4*)(qkv + (size_t)ktok * QKVD + DIMN + h * DHEAD);
            const float4* sv = (const float4*)(qkv + (size_t)ktok * QKVD + 2 * DIMN + h * DHEAD);
            float4* dK = (float4*)&sK[r][0];
            float4* dV = (float4*)&sV[r][0];
#pragma unroll
            for (int f = 0; f < 8; ++f) { dK[f0 + f] = sk[f0 + f]; dV[f0 + f] = sv[f0 + f]; }
        }
        __syncthreads();

        // ---- K transform in smem: thread (2r+half) owns dims [d0,d0+16)+[d0+32,d0+48)
        {
            int r  = i >> 1;
            int d0 = (i & 1) * 16;
            int ktok = tok0 + c * 64 - WIN + r;
            int n = ktok & (SEQ - 1);
            float lo[16], hi[16];
            *(float4*)&lo[0]  = *(float4*)&sK[r][d0 + 0];
            *(float4*)&lo[4]  = *(float4*)&sK[r][d0 + 4];
            *(float4*)&lo[8]  = *(float4*)&sK[r][d0 + 8];
            *(float4*)&lo[12] = *(float4*)&sK[r][d0 + 12];
            *(float4*)&hi[0]  = *(float4*)&sK[r][d0 + 32];
            *(float4*)&hi[4]  = *(float4*)&sK[r][d0 + 36];
            *(float4*)&hi[8]  = *(float4*)&sK[r][d0 + 40];
            *(float4*)&hi[12] = *(float4*)&sK[r][d0 + 44];
            float ssq = 0.f;
#pragma unroll
            for (int t = 0; t < 16; ++t) ssq += lo[t] * lo[t] + hi[t] * hi[t];
            ssq += __shfl_xor_sync(0xffffffffu, ssq, 1);
            float inv = 1.0f / fmaxf(sqrtf(ssq), 1e-12f);
            const float* rcn = rc + n * 32 + d0;
            const float* rsn = rs + n * 32 + d0;
#pragma unroll
            for (int t = 0; t < 16; ++t) {
                int d = d0 + t;
                float a  = lo[t] * inv * sKsc[d];
                float bb = hi[t] * inv * sKsc[d + 32];
                float c_ = rcn[t], s_ = rsn[t];
                lo[t] = a * c_ - bb * s_;
                hi[t] = bb * c_ + a * s_;
            }
            *(float4*)&sK[r][d0 + 0]  = *(float4*)&lo[0];
            *(float4*)&sK[r][d0 + 4]  = *(float4*)&lo[4];
            *(float4*)&sK[r][d0 + 8]  = *(float4*)&lo[8];
            *(float4*)&sK[r][d0 + 12] = *(float4*)&lo[12];
            *(float4*)&sK[r][d0 + 32] = *(float4*)&hi[0];
            *(float4*)&sK[r][d0 + 36] = *(float4*)&hi[4];
            *(float4*)&sK[r][d0 + 40] = *(float4*)&hi[8];
            *(float4*)&sK[r][d0 + 44] = *(float4*)&hi[12];
        }
        __syncthreads();

        int jmax;
        if (c < 2) jmax = 64;
        else {
            jmax = i - (c - 2) * 64 + 1;
            jmax = jmax < 0 ? 0 : (jmax > 64 ? 64 : jmax);
        }
        for (int j = 0; j < jmax; ++j) {
            const ulonglong2* kr = (const ulonglong2*)&sK[j][0];
            unsigned long long s0 = 0ull, s1 = 0ull, s2 = 0ull, s3 = 0ull;
#pragma unroll
            for (int d = 0; d < 16; ++d) {           // 16 ulonglong2 = 64 floats
                ulonglong2 kk = kr[d];
                if (d & 1) {
                    s2 = ffma2(q2[2 * d],     kk.x, s2);
                    s3 = ffma2(q2[2 * d + 1], kk.y, s3);
                } else {
                    s0 = ffma2(q2[2 * d],     kk.x, s0);
                    s1 = ffma2(q2[2 * d + 1], kk.y, s1);
                }
            }
            unsigned long long tsum = addf2(addf2(s0, s1), addf2(s2, s3));
            float2 tf = unpack2(tsum);
            float sc = (tf.x + tf.y) * 8.0f;   // QK_SCALE; |sc|<=8 (l2-normed q,k)
            float p  = __expf(sc);             // no overflow; offset-free softmax
            l += p;
            unsigned long long pp = pack2(p, p);
            const ulonglong2* vr = (const ulonglong2*)&sV[j][0];
#pragma unroll
            for (int d = 0; d < 16; ++d) {
                ulonglong2 vv = vr[d];
                acc2[2 * d]     = ffma2(pp, vv.x, acc2[2 * d]);
                acc2[2 * d + 1] = ffma2(pp, vv.y, acc2[2 * d + 1]);
            }
        }
    }

    float invl = 1.0f / l;
    size_t dstoff = (size_t)tok * DIMN + h * DHEAD;
#pragma unroll
    for (int g = 0; g < 8; ++g) {
        uint32_t hp[4];
#pragma unroll
        for (int k = 0; k < 4; ++k) {
            float2 f = unpack2(acc2[g * 4 + k]);
            __half2 hh = __floats2half2_rn(f.x * invl, f.y * invl);
            hp[k] = *(uint32_t*)&hh;
        }
        *(uint4*)(oh + dstoff + g * 8) = make_uint4(hp[0], hp[1], hp[2], hp[3]);
    }
}

// ====== HMMA GEMM fp16, double-buffered cp.async, 2 CTAs/SM (R11 config) =======
#define KBLK     64
#define TILE_B   16384
#define STAGE_B  (2 * TILE_B)
#define SM_TOTAL (2 * STAGE_B)

__device__ __forceinline__ float gelu_f(float x)
{
    return 0.5f * x * (1.0f + erff(x * 0.7071067811865476f));
}

template <int EPI>   // 0 fp32 | 1 +bias+resid fp32 | 2 gelu->fp16 | 3 +resid fp32
__global__ __launch_bounds__(256, 2) void gemm_tc(
    const __half* __restrict__ A, const __half* __restrict__ B,
    int M, int N, int K,
    float* __restrict__ Cf, __half* __restrict__ Ch,
    const float* __restrict__ bias, const float* __restrict__ resid)
{
    extern __shared__ char smem[];
    uint32_t sb = smem_u32(smem);
    int tid = threadIdx.x, wid = tid >> 5, lane = tid & 31;
    int warpM = wid & 3, warpN = wid >> 2;
    int bm = blockIdx.y * 128, bn = blockIdx.x * 128;

    float acc[2][8][4];
#pragma unroll
    for (int mi = 0; mi < 2; ++mi)
#pragma unroll
        for (int ni = 0; ni < 8; ++ni)
#pragma unroll
            for (int r = 0; r < 4; ++r) acc[mi][ni][r] = 0.f;

    int aRow  = lane & 15;
    int aKoff = (lane >> 4) << 3;
    int bRow  = (lane & 7) + ((lane >> 4) << 3);
    int bKoff = ((lane >> 3) & 1) << 3;

    int ldRow = tid >> 3, ldC16 = tid & 7;

    int kchunks = K / KBLK;

#pragma unroll
    for (int tile = 0; tile < 2; ++tile) {
        const __half* src = (tile == 0) ? A : B;
        int rbase = (tile == 0) ? bm : bn;
        uint32_t dstb = sb + tile * TILE_B;
#pragma unroll
        for (int it = 0; it < 4; ++it) {
            int row = ldRow + it * 32;
            cp_async16(dstb + SWZ(row * 128 + ldC16 * 16),
                       src + (size_t)(rbase + row) * K + ldC16 * 8);
        }
    }
    cp_commit();

#pragma unroll 1
    for (int kc = 0; kc < kchunks; ++kc) {
        uint32_t cur = sb + (uint32_t)(kc & 1) * STAGE_B;
        if (kc + 1 < kchunks) {
            uint32_t nxt = sb + (uint32_t)((kc + 1) & 1) * STAGE_B;
            int k0 = (kc + 1) * KBLK;
#pragma unroll
            for (int tile = 0; tile < 2; ++tile) {
                const __half* src = (tile == 0) ? A : B;
                int rbase = (tile == 0) ? bm : bn;
                uint32_t dstb = nxt + tile * TILE_B;
#pragma unroll
                for (int it = 0; it < 4; ++it) {
                    int row = ldRow + it * 32;
                    cp_async16(dstb + SWZ(row * 128 + ldC16 * 16),
                               src + (size_t)(rbase + row) * K + k0 + ldC16 * 8);
                }
            }
            cp_commit();
            cp_wait<1>();
        } else {
            cp_wait<0>();
        }
        __syncthreads();

#pragma unroll
        for (int k16 = 0; k16 < KBLK / 16; ++k16) {
            uint32_t aOff  = SWZ((warpM * 32 + aRow) * 128 + (k16 * 16 + aKoff) * 2);
            uint32_t aOff2 = SWZ((warpM * 32 + 16 + aRow) * 128 + (k16 * 16 + aKoff) * 2);
            uint32_t a[2][4], b[8][2];

            ldmatrix_x4(a[0][0], a[0][1], a[0][2], a[0][3], cur + aOff);
            ldmatrix_x4(a[1][0], a[1][1], a[1][2], a[1][3], cur + aOff2);
#pragma unroll
            for (int np = 0; np < 4; ++np) {
                uint32_t bo = SWZ((warpN * 64 + np * 16 + bRow) * 128 +
                                  (k16 * 16 + bKoff) * 2);
                ldmatrix_x4(b[np * 2][0], b[np * 2][1],
                            b[np * 2 + 1][0], b[np * 2 + 1][1], cur + TILE_B + bo);
            }
#pragma unroll
            for (int mi = 0; mi < 2; ++mi)
#pragma unroll
                for (int ni = 0; ni < 8; ++ni)
                    mma_fp16(acc[mi][ni], a[mi], b[ni]);
        }
        __syncthreads();
    }

#pragma unroll
    for (int mi = 0; mi < 2; ++mi)
#pragma unroll
        for (int ni = 0; ni < 8; ++ni) {
            int row = bm + warpM * 32 + mi * 16 + (lane >> 2);
            int col = bn + warpN * 64 + ni * 8 + (lane & 3) * 2;
#pragma unroll
            for (int hh = 0; hh < 2; ++hh) {
                int r = row + hh * 8;
                float v0 = acc[mi][ni][hh * 2 + 0] * WSCALE_INV;
                float v1 = acc[mi][ni][hh * 2 + 1] * WSCALE_INV;
                size_t idx = (size_t)r * N + col;
                if (EPI == 2) {
                    __half2 hp = __floats2half2_rn(gelu_f(v0), gelu_f(v1));
                    *(uint32_t*)(Ch + idx) = *(uint32_t*)&hp;
                } else {
                    if (EPI == 1) {
                        float2 rs = *(const float2*)(resid + idx);
                        v0 += bias[col] + rs.x;
                        v1 += bias[col + 1] + rs.y;
                    } else if (EPI == 3) {
                        float2 rs = *(const float2*)(resid + idx);
                        v0 += rs.x; v1 += rs.y;
                    }
                    *(float2*)(Cf + idx) = make_float2(v0, v1);
                }
            }
        }
}

// ------------------------------- launch ---------------------------------------
extern "C" void kernel_launch(void* const* d_in, const int* in_sizes, int n_in,
                              void* d_out, int out_size)
{
    const float* x       = (const float*)d_in[0];
    const float* w_qkv   = (const float*)d_in[1];
    const float* q_scale = (const float*)d_in[2];
    const float* k_scale = (const float*)d_in[3];
    const float* w_out   = (const float*)d_in[4];
    const float* b_out   = (const float*)d_in[5];
    const float* ln1_g   = (const float*)d_in[6];
    const float* ln1_b   = (const float*)d_in[7];
    const float* ff_ln_g = (const float*)d_in[8];
    const float* ff_ln_b = (const float*)d_in[9];
    const float* w_ff1   = (const float*)d_in[10];
    const float* w_ff2   = (const float*)d_in[11];
    float* out = (float*)d_out;

    float *p_qkv, *p_x1, *p_rotc, *p_rots;
    __half *p_h, *p_at, *p_f1, *p_wqkv, *p_wout, *p_wff1, *p_wff2;
    cudaGetSymbolAddress((void**)&p_qkv, g_qkv);
    cudaGetSymbolAddress((void**)&p_x1, g_x1);
    cudaGetSymbolAddress((void**)&p_rotc, g_rotc);
    cudaGetSymbolAddress((void**)&p_rots, g_rots);
    cudaGetSymbolAddress((void**)&p_h, g_h);
    cudaGetSymbolAddress((void**)&p_at, g_at);
    cudaGetSymbolAddress((void**)&p_f1, g_f1);
    cudaGetSymbolAddress((void**)&p_wqkv, g_wqkv);
    cudaGetSymbolAddress((void**)&p_wout, g_wout);
    cudaGetSymbolAddress((void**)&p_wff1, g_wff1);
    cudaGetSymbolAddress((void**)&p_wff2, g_wff2);

    cudaFuncSetAttribute(gemm_tc<0>, cudaFuncAttributeMaxDynamicSharedMemorySize, SM_TOTAL);
    cudaFuncSetAttribute(gemm_tc<1>, cudaFuncAttributeMaxDynamicSharedMemorySize, SM_TOTAL);
    cudaFuncSetAttribute(gemm_tc<2>, cudaFuncAttributeMaxDynamicSharedMemorySize, SM_TOTAL);
    cudaFuncSetAttribute(gemm_tc<3>, cudaFuncAttributeMaxDynamicSharedMemorySize, SM_TOTAL);

    // rotary table + weight converts (independent of LN/GEMM0 chain)
    rotary_kernel<<<(SEQ * 32) / 256, 256>>>(p_rotc, p_rots);
    wconv_kernel<<<(QKVD * DIMN / 4 + 255) / 256, 256>>>(w_qkv, p_wqkv, QKVD * DIMN / 4);
    wconv_kernel<<<(DIMN * DIMN / 4 + 255) / 256, 256>>>(w_out, p_wout, DIMN * DIMN / 4);
    wconv_kernel<<<(FFD * DIMN / 4 + 255) / 256, 256>>>(w_ff1, p_wff1, FFD * DIMN / 4);
    wconv_kernel<<<(DIMN * FFD / 4 + 255) / 256, 256>>>(w_ff2, p_wff2, DIMN * FFD / 4);

    // 1) h = LN1(x) -> fp16
    ln_kernel<<<NTOK, 128>>>(x, ln1_g, ln1_b, p_h);

    // 2) qkv = h @ w_qkv^T (fp32 out, raw q/k — transform fused into attention)
    gemm_tc<0><<<dim3(QKVD / 128, NTOK / 128), 256, SM_TOTAL>>>(
        p_h, p_wqkv, NTOK, QKVD, DIMN, p_qkv, nullptr, nullptr, nullptr);

    // 3) attention (fused l2norm+scale+rotary) -> fp16
    attn_kernel<<<dim3(NW, HEADS, BATCH), 128>>>(p_qkv, q_scale, k_scale,
                                                 p_rotc, p_rots, p_at);

    // 4) x1 = x + attn @ w_out^T + b_out
    gemm_tc<1><<<dim3(DIMN / 128, NTOK / 128), 256, SM_TOTAL>>>(
        p_at, p_wout, NTOK, DIMN, DIMN, p_x1, nullptr, b_out, x);

    // 5) h = LN2(x1) -> fp16
    ln_kernel<<<NTOK, 128>>>(p_x1, ff_ln_g, ff_ln_b, p_h);

    // 6) ff1 = gelu(h @ w_ff1^T) -> fp16
    gemm_tc<2><<<dim3(FFD / 128, NTOK / 128), 256, SM_TOTAL>>>(
        p_h, p_wff1, NTOK, FFD, DIMN, nullptr, p_f1, nullptr, nullptr);

    // 7) out = x1 + ff1 @ w_ff2^T
    gemm_tc<3><<<dim3(DIMN / 128, NTOK / 128), 256, SM_TOTAL>>>(
        p_f1, p_wff2, NTOK, DIMN, FFD, out, nullptr, nullptr, p_x1);
}

// round 15
// speedup vs baseline: 1.0333x; 1.0333x over previous
#include <cuda_runtime.h>
#include <cuda_bf16.h>
#include <cuda_fp16.h>
#include <stdint.h>
#include <math.h>

#define BATCH   8
#define SEQ     4096
#define DIMN    512
#define HEADS   8
#define DHEAD   64
#define WIN     128
#define NW      (SEQ / WIN)
#define NTOK    (BATCH * SEQ)
#define QKVD    (3 * DIMN)
#define FFD     (4 * DIMN)

#define WSCALE     512.0f            // weights pre-scaled by 512 (exact pow2)
#define WSCALE_INV (1.0f / 512.0f)

// ======================= scratch (static device memory) ========================
__device__ float  g_qkv [(size_t)NTOK * QKVD];
__device__ float  g_x1  [(size_t)NTOK * DIMN];
__device__ __half g_h   [(size_t)NTOK * DIMN];
__device__ __half g_at  [(size_t)NTOK * DIMN];
__device__ __half g_f1  [(size_t)NTOK * FFD];
__device__ __half g_wqkv[QKVD * DIMN];
__device__ __half g_wout[DIMN * DIMN];
__device__ __half g_wff1[FFD * DIMN];
__device__ __half g_wff2[DIMN * FFD];
__device__ float  g_rotc[SEQ * 32];   // rotary cos table [pos][lane]
__device__ float  g_rots[SEQ * 32];   // rotary sin table

// ============================ helpers ==========================================
__device__ __forceinline__ uint32_t smem_u32(const void* p) {
    uint32_t a;
    asm("{ .reg .u64 t; cvta.to.shared.u64 t, %1; cvt.u32.u64 %0, t; }" : "=r"(a) : "l"(p));
    return a;
}
#define SWZ(o) ((o) ^ (((o) >> 3) & 0x70))   // SW128 swizzle, 128B rows

__device__ __forceinline__ void cp_async16(uint32_t dst, const void* src) {
    asm volatile("cp.async.cg.shared.global [%0], [%1], 16;" :: "r"(dst), "l"(src));
}
__device__ __forceinline__ void cp_commit() {
    asm volatile("cp.async.commit_group;");
}
template <int N>
__device__ __forceinline__ void cp_wait() {
    asm volatile("cp.async.wait_group %0;" :: "n"(N));
}
__device__ __forceinline__ void ldmatrix_x4(uint32_t& r0, uint32_t& r1,
                                            uint32_t& r2, uint32_t& r3, uint32_t a) {
    asm volatile("ldmatrix.sync.aligned.m8n8.x4.shared.b16 {%0,%1,%2,%3}, [%4];"
                 : "=r"(r0), "=r"(r1), "=r"(r2), "=r"(r3) : "r"(a));
}
__device__ __forceinline__ void mma_fp16(float* c, const uint32_t* a, const uint32_t* b) {
    asm volatile("mma.sync.aligned.m16n8k16.row.col.f32.f16.f16.f32 "
                 "{%0,%1,%2,%3}, {%4,%5,%6,%7}, {%8,%9}, {%0,%1,%2,%3};"
                 : "+f"(c[0]), "+f"(c[1]), "+f"(c[2]), "+f"(c[3])
                 : "r"(a[0]), "r"(a[1]), "r"(a[2]), "r"(a[3]), "r"(b[0]), "r"(b[1]));
}

// ---- packed fp32x2 (Blackwell): 2 IEEE fp32 ops per instruction ----
__device__ __forceinline__ unsigned long long ffma2(unsigned long long a,
                                                    unsigned long long b,
                                                    unsigned long long c) {
    unsigned long long d;
    asm("fma.rn.f32x2 %0, %1, %2, %3;" : "=l"(d) : "l"(a), "l"(b), "l"(c));
    return d;
}
__device__ __forceinline__ unsigned long long addf2(unsigned long long a,
                                                    unsigned long long b) {
    unsigned long long d;
    asm("add.rn.f32x2 %0, %1, %2;" : "=l"(d) : "l"(a), "l"(b));
    return d;
}
__device__ __forceinline__ float2 unpack2(unsigned long long v) {
    float2 r;
    asm("mov.b64 {%0, %1}, %2;" : "=f"(r.x), "=f"(r.y) : "l"(v));
    return r;
}
__device__ __forceinline__ unsigned long long pack2(float x, float y) {
    unsigned long long v;
    asm("mov.b64 %0, {%1, %2};" : "=l"(v) : "f"(x), "f"(y));
    return v;
}

// ================= LayerNorm -> fp16. block = token =============================
__global__ __launch_bounds__(128) void ln_kernel(const float* __restrict__ in,
                                                 const float* __restrict__ gamma,
                                                 const float* __restrict__ beta,
                                                 __half* __restrict__ oh)
{
    int t = blockIdx.x;
    int tid = threadIdx.x;
    const float4* row = (const float4*)(in + (size_t)t * DIMN);
    float4 v = row[tid];
    float s  = v.x + v.y + v.z + v.w;
    float ss = v.x * v.x + v.y * v.y + v.z * v.z + v.w * v.w;
#pragma unroll
    for (int o = 16; o > 0; o >>= 1) {
        s  += __shfl_xor_sync(0xffffffffu, s, o);
        ss += __shfl_xor_sync(0xffffffffu, ss, o);
    }
    __shared__ float sm[4], sm2[4];
    int w = tid >> 5, lane = tid & 31;
    if (lane == 0) { sm[w] = s; sm2[w] = ss; }
    __syncthreads();
    s  = sm[0] + sm[1] + sm[2] + sm[3];
    ss = sm2[0] + sm2[1] + sm2[2] + sm2[3];
    float mean = s * (1.0f / DIMN);
    float var  = ss * (1.0f / DIMN) - mean * mean;
    float inv  = rsqrtf(var + 1e-5f);
    float4 g = ((const float4*)gamma)[tid];
    float4 b = ((const float4*)beta)[tid];
    float o0 = (v.x - mean) * inv * g.x + b.x;
    float o1 = (v.y - mean) * inv * g.y + b.y;
    float o2 = (v.z - mean) * inv * g.z + b.z;
    float o3 = (v.w - mean) * inv * g.w + b.w;
    __half2 p0 = __floats2half2_rn(o0, o1);
    __half2 p1 = __floats2half2_rn(o2, o3);
    *(uint2*)(oh + (size_t)t * DIMN + tid * 4) = make_uint2(*(uint32_t*)&p0, *(uint32_t*)&p1);
}

// ========= weight convert: fp32 -> fp16 of (512 * w) ============================
__global__ void wconv_kernel(const float* __restrict__ in,
                             __half* __restrict__ oh, int n4)
{
    int i = blockIdx.x * blockDim.x + threadIdx.x;
    if (i >= n4) return;
    float4 v = ((const float4*)in)[i];
    __half2 p0 = __floats2half2_rn(v.x * WSCALE, v.y * WSCALE);
    __half2 p1 = __floats2half2_rn(v.z * WSCALE, v.w * WSCALE);
    ((uint2*)oh)[i] = make_uint2(*(uint32_t*)&p0, *(uint32_t*)&p1);
}

// ========= rotary table: cos/sin of fp32 phase, exact double trig ===============
__global__ void rotary_kernel(float* __restrict__ rc, float* __restrict__ rs)
{
    int idx = blockIdx.x * blockDim.x + threadIdx.x;   // SEQ*32
    int n = idx >> 5, lane = idx & 31;
    double invf_d = exp(-(double)(2 * lane) * (9.210340371976184 / 64.0));
    float ph = (float)n * (float)invf_d;               // fp32 phase (matches ref)
    double sd, cd;
    sincos((double)ph, &sd, &cd);
    rc[idx] = (float)cd;
    rs[idx] = (float)sd;
}

// ========= K-only post: l2norm*scale + rotary (table lookup) ====================
// Q transform is fused into attention (once per query, in registers). K stays
// here: fusing K caused 2x redundant work + extra barriers (R14 regression).
__global__ __launch_bounds__(256) void qkpost_k_kernel(float* __restrict__ qkv,
                                                       const float* __restrict__ ksc,
                                                       const float* __restrict__ rc,
                                                       const float* __restrict__ rs)
{
    int t = blockIdx.x;
    int n = t & (SEQ - 1);
    int h = threadIdx.x >> 5;
    int lane = threadIdx.x & 31;

    float c = rc[n * 32 + lane];
    float s = rs[n * 32 + lane];

    float* kb = qkv + (size_t)t * QKVD + DIMN + h * DHEAD;
    float a = kb[lane], b = kb[lane + 32];
    float ssq = a * a + b * b;
#pragma unroll
    for (int o = 16; o > 0; o >>= 1) ssq += __shfl_xor_sync(0xffffffffu, ssq, o);
    float inv = 1.0f / fmaxf(sqrtf(ssq), 1e-12f);
    float an = a * inv * ksc[lane];
    float bn = b * inv * ksc[lane + 32];
    kb[lane]      = an * c - bn * s;
    kb[lane + 32] = bn * c + an * s;
}

// ====== local-window attention: fused Q transform + f32x2 math =================
// Q: raw load -> l2norm*scale+rotary in registers (once per thread, no syncs).
// K arrives pre-transformed from qkpost_k. Fixed-offset softmax (|sc|<=8).
__global__ __launch_bounds__(128) void attn_kernel(const float* __restrict__ qkv,
                                                   const float* __restrict__ qsc,
                                                   const float* __restrict__ rc,
                                                   const float* __restrict__ rs,
                                                   __half* __restrict__ oh)
{
    __shared__ float sK[64][DHEAD];
    __shared__ float sV[64][DHEAD];

    int w = blockIdx.x, h = blockIdx.y, b = blockIdx.z;
    int i = threadIdx.x;
    int tok0 = b * SEQ + w * WIN;
    int tok  = tok0 + i;

    // ---- Q: load raw, l2norm*scale + rotary in registers, pack to f32x2 ----
    unsigned long long q2[32];
    {
        float qv[64];
        const float4* srcQ = (const float4*)(qkv + (size_t)tok * QKVD + h * DHEAD);
#pragma unroll
        for (int d4 = 0; d4 < 16; ++d4) {
            float4 t4 = srcQ[d4];
            qv[d4 * 4 + 0] = t4.x; qv[d4 * 4 + 1] = t4.y;
            qv[d4 * 4 + 2] = t4.z; qv[d4 * 4 + 3] = t4.w;
        }
        float ssq = 0.f;
#pragma unroll
        for (int d = 0; d < 64; ++d) ssq += qv[d] * qv[d];
        float inv = 1.0f / fmaxf(sqrtf(ssq), 1e-12f);
        int n = tok & (SEQ - 1);
        const float* rcn = rc + n * 32;
        const float* rsn = rs + n * 32;
#pragma unroll
        for (int d = 0; d < 32; ++d) {
            float a  = qv[d] * inv * qsc[d];
            float bb = qv[d + 32] * inv * qsc[d + 32];
            float c_ = rcn[d], s_ = rsn[d];
            qv[d]      = a * c_ - bb * s_;
            qv[d + 32] = bb * c_ + a * s_;
        }
#pragma unroll
        for (int j = 0; j < 32; ++j) q2[j] = pack2(qv[2 * j], qv[2 * j + 1]);
    }

    unsigned long long acc2[32];
#pragma unroll
    for (int d = 0; d < 32; ++d) acc2[d] = 0ull;
    float l = 0.f;

#pragma unroll 1
    for (int c = 0; c < 4; ++c) {
        if (c < 2 && w == 0) continue;

        __syncthreads();
        {
            int r  = i >> 1;
            int f0 = (i & 1) * 8;
            int ktok = tok0 + c * 64 - WIN + r;
            const float4* sk = (const float4*)(qkv + (size_t)ktok * QKVD + DIMN + h * DHEAD);
            const float4* sv = (const float4*)(qkv + (size_t)ktok * QKVD + 2 * DIMN + h * DHEAD);
            float4* dK = (float4*)&sK[r][0];
            float4* dV = (float4*)&sV[r][0];
#pragma unroll
            for (int f = 0; f < 8; ++f) { dK[f0 + f] = sk[f0 + f]; dV[f0 + f] = sv[f0 + f]; }
        }
        __syncthreads();

        int jmax;
        if (c < 2) jmax = 64;
        else {
            jmax = i - (c - 2) * 64 + 1;
            jmax = jmax < 0 ? 0 : (jmax > 64 ? 64 : jmax);
        }
        for (int j = 0; j < jmax; ++j) {
            const ulonglong2* kr = (const ulonglong2*)&sK[j][0];
            unsigned long long s0 = 0ull, s1 = 0ull, s2 = 0ull, s3 = 0ull;
#pragma unroll
            for (int d = 0; d < 16; ++d) {           // 16 ulonglong2 = 64 floats
                ulonglong2 kk = kr[d];
                if (d & 1) {
                    s2 = ffma2(q2[2 * d],     kk.x, s2);
                    s3 = ffma2(q2[2 * d + 1], kk.y, s3);
                } else {
                    s0 = ffma2(q2[2 * d],     kk.x, s0);
                    s1 = ffma2(q2[2 * d + 1], kk.y, s1);
                }
            }
            unsigned long long tsum = addf2(addf2(s0, s1), addf2(s2, s3));
            float2 tf = unpack2(tsum);
            float sc = (tf.x + tf.y) * 8.0f;   // QK_SCALE; |sc|<=8 (l2-normed q,k)
            float p  = __expf(sc);             // no overflow; offset-free softmax
            l += p;
            unsigned long long pp = pack2(p, p);
            const ulonglong2* vr = (const ulonglong2*)&sV[j][0];
#pragma unroll
            for (int d = 0; d < 16; ++d) {
                ulonglong2 vv = vr[d];
                acc2[2 * d]     = ffma2(pp, vv.x, acc2[2 * d]);
                acc2[2 * d + 1] = ffma2(pp, vv.y, acc2[2 * d + 1]);
            }
        }
    }

    float invl = 1.0f / l;
    size_t dstoff = (size_t)tok * DIMN + h * DHEAD;
#pragma unroll
    for (int g = 0; g < 8; ++g) {
        uint32_t hp[4];
#pragma unroll
        for (int k = 0; k < 4; ++k) {
            float2 f = unpack2(acc2[g * 4 + k]);
            __half2 hh = __floats2half2_rn(f.x * invl, f.y * invl);
            hp[k] = *(uint32_t*)&hh;
        }
        *(uint4*)(oh + dstoff + g * 8) = make_uint4(hp[0], hp[1], hp[2], hp[3]);
    }
}

// ====== HMMA GEMM fp16, double-buffered cp.async, 2 CTAs/SM (R11 config) =======
#define KBLK     64
#define TILE_B   16384
#define STAGE_B  (2 * TILE_B)
#define SM_TOTAL (2 * STAGE_B)

__device__ __forceinline__ float gelu_f(float x)
{
    return 0.5f * x * (1.0f + erff(x * 0.7071067811865476f));
}

template <int EPI>   // 0 fp32 | 1 +bias+resid fp32 | 2 gelu->fp16 | 3 +resid fp32
__global__ __launch_bounds__(256, 2) void gemm_tc(
    const __half* __restrict__ A, const __half* __restrict__ B,
    int M, int N, int K,
    float* __restrict__ Cf, __half* __restrict__ Ch,
    const float* __restrict__ bias, const float* __restrict__ resid)
{
    extern __shared__ char smem[];
    uint32_t sb = smem_u32(smem);
    int tid = threadIdx.x, wid = tid >> 5, lane = tid & 31;
    int warpM = wid & 3, warpN = wid >> 2;
    int bm = blockIdx.y * 128, bn = blockIdx.x * 128;

    float acc[2][8][4];
#pragma unroll
    for (int mi = 0; mi < 2; ++mi)
#pragma unroll
        for (int ni = 0; ni < 8; ++ni)
#pragma unroll
            for (int r = 0; r < 4; ++r) acc[mi][ni][r] = 0.f;

    int aRow  = lane & 15;
    int aKoff = (lane >> 4) << 3;
    int bRow  = (lane & 7) + ((lane >> 4) << 3);
    int bKoff = ((lane >> 3) & 1) << 3;

    int ldRow = tid >> 3, ldC16 = tid & 7;

    int kchunks = K / KBLK;

#pragma unroll
    for (int tile = 0; tile < 2; ++tile) {
        const __half* src = (tile == 0) ? A : B;
        int rbase = (tile == 0) ? bm : bn;
        uint32_t dstb = sb + tile * TILE_B;
#pragma unroll
        for (int it = 0; it < 4; ++it) {
            int row = ldRow + it * 32;
            cp_async16(dstb + SWZ(row * 128 + ldC16 * 16),
                       src + (size_t)(rbase + row) * K + ldC16 * 8);
        }
    }
    cp_commit();

#pragma unroll 1
    for (int kc = 0; kc < kchunks; ++kc) {
        uint32_t cur = sb + (uint32_t)(kc & 1) * STAGE_B;
        if (kc + 1 < kchunks) {
            uint32_t nxt = sb + (uint32_t)((kc + 1) & 1) * STAGE_B;
            int k0 = (kc + 1) * KBLK;
#pragma unroll
            for (int tile = 0; tile < 2; ++tile) {
                const __half* src = (tile == 0) ? A : B;
                int rbase = (tile == 0) ? bm : bn;
                uint32_t dstb = nxt + tile * TILE_B;
#pragma unroll
                for (int it = 0; it < 4; ++it) {
                    int row = ldRow + it * 32;
                    cp_async16(dstb + SWZ(row * 128 + ldC16 * 16),
                               src + (size_t)(rbase + row) * K + k0 + ldC16 * 8);
                }
            }
            cp_commit();
            cp_wait<1>();
        } else {
            cp_wait<0>();
        }
        __syncthreads();

#pragma unroll
        for (int k16 = 0; k16 < KBLK / 16; ++k16) {
            uint32_t aOff  = SWZ((warpM * 32 + aRow) * 128 + (k16 * 16 + aKoff) * 2);
            uint32_t aOff2 = SWZ((warpM * 32 + 16 + aRow) * 128 + (k16 * 16 + aKoff) * 2);
            uint32_t a[2][4], b[8][2];

            ldmatrix_x4(a[0][0], a[0][1], a[0][2], a[0][3], cur + aOff);
            ldmatrix_x4(a[1][0], a[1][1], a[1][2], a[1][3], cur + aOff2);
#pragma unroll
            for (int np = 0; np < 4; ++np) {
                uint32_t bo = SWZ((warpN * 64 + np * 16 + bRow) * 128 +
                                  (k16 * 16 + bKoff) * 2);
                ldmatrix_x4(b[np * 2][0], b[np * 2][1],
                            b[np * 2 + 1][0], b[np * 2 + 1][1], cur + TILE_B + bo);
            }
#pragma unroll
            for (int mi = 0; mi < 2; ++mi)
#pragma unroll
                for (int ni = 0; ni < 8; ++ni)
                    mma_fp16(acc[mi][ni], a[mi], b[ni]);
        }
        __syncthreads();
    }

#pragma unroll
    for (int mi = 0; mi < 2; ++mi)
#pragma unroll
        for (int ni = 0; ni < 8; ++ni) {
            int row = bm + warpM * 32 + mi * 16 + (lane >> 2);
            int col = bn + warpN * 64 + ni * 8 + (lane & 3) * 2;
#pragma unroll
            for (int hh = 0; hh < 2; ++hh) {
                int r = row + hh * 8;
                float v0 = acc[mi][ni][hh * 2 + 0] * WSCALE_INV;
                float v1 = acc[mi][ni][hh * 2 + 1] * WSCALE_INV;
                size_t idx = (size_t)r * N + col;
                if (EPI == 2) {
                    __half2 hp = __floats2half2_rn(gelu_f(v0), gelu_f(v1));
                    *(uint32_t*)(Ch + idx) = *(uint32_t*)&hp;
                } else {
                    if (EPI == 1) {
                        float2 rs = *(const float2*)(resid + idx);
                        v0 += bias[col] + rs.x;
                        v1 += bias[col + 1] + rs.y;
                    } else if (EPI == 3) {
                        float2 rs = *(const float2*)(resid + idx);
                        v0 += rs.x; v1 += rs.y;
                    }
                    *(float2*)(Cf + idx) = make_float2(v0, v1);
                }
            }
        }
}

// ------------------------------- launch ---------------------------------------
extern "C" void kernel_launch(void* const* d_in, const int* in_sizes, int n_in,
                              void* d_out, int out_size)
{
    const float* x       = (const float*)d_in[0];
    const float* w_qkv   = (const float*)d_in[1];
    const float* q_scale = (const float*)d_in[2];
    const float* k_scale = (const float*)d_in[3];
    const float* w_out   = (const float*)d_in[4];
    const float* b_out   = (const float*)d_in[5];
    const float* ln1_g   = (const float*)d_in[6];
    const float* ln1_b   = (const float*)d_in[7];
    const float* ff_ln_g = (const float*)d_in[8];
    const float* ff_ln_b = (const float*)d_in[9];
    const float* w_ff1   = (const float*)d_in[10];
    const float* w_ff2   = (const float*)d_in[11];
    float* out = (float*)d_out;

    float *p_qkv, *p_x1, *p_rotc, *p_rots;
    __half *p_h, *p_at, *p_f1, *p_wqkv, *p_wout, *p_wff1, *p_wff2;
    cudaGetSymbolAddress((void**)&p_qkv, g_qkv);
    cudaGetSymbolAddress((void**)&p_x1, g_x1);
    cudaGetSymbolAddress((void**)&p_rotc, g_rotc);
    cudaGetSymbolAddress((void**)&p_rots, g_rots);
    cudaGetSymbolAddress((void**)&p_h, g_h);
    cudaGetSymbolAddress((void**)&p_at, g_at);
    cudaGetSymbolAddress((void**)&p_f1, g_f1);
    cudaGetSymbolAddress((void**)&p_wqkv, g_wqkv);
    cudaGetSymbolAddress((void**)&p_wout, g_wout);
    cudaGetSymbolAddress((void**)&p_wff1, g_wff1);
    cudaGetSymbolAddress((void**)&p_wff2, g_wff2);

    cudaFuncSetAttribute(gemm_tc<0>, cudaFuncAttributeMaxDynamicSharedMemorySize, SM_TOTAL);
    cudaFuncSetAttribute(gemm_tc<1>, cudaFuncAttributeMaxDynamicSharedMemorySize, SM_TOTAL);
    cudaFuncSetAttribute(gemm_tc<2>, cudaFuncAttributeMaxDynamicSharedMemorySize, SM_TOTAL);
    cudaFuncSetAttribute(gemm_tc<3>, cudaFuncAttributeMaxDynamicSharedMemorySize, SM_TOTAL);

    // rotary table + weight converts
    rotary_kernel<<<(SEQ * 32) / 256, 256>>>(p_rotc, p_rots);
    wconv_kernel<<<(QKVD * DIMN / 4 + 255) / 256, 256>>>(w_qkv, p_wqkv, QKVD * DIMN / 4);
    wconv_kernel<<<(DIMN * DIMN / 4 + 255) / 256, 256>>>(w_out, p_wout, DIMN * DIMN / 4);
    wconv_kernel<<<(FFD * DIMN / 4 + 255) / 256, 256>>>(w_ff1, p_wff1, FFD * DIMN / 4);
    wconv_kernel<<<(DIMN * FFD / 4 + 255) / 256, 256>>>(w_ff2, p_wff2, DIMN * FFD / 4);

    // 1) h = LN1(x) -> fp16
    ln_kernel<<<NTOK, 128>>>(x, ln1_g, ln1_b, p_h);

    // 2) qkv = h @ w_qkv^T (fp32 out; q stays raw, transformed in attention)
    gemm_tc<0><<<dim3(QKVD / 128, NTOK / 128), 256, SM_TOTAL>>>(
        p_h, p_wqkv, NTOK, QKVD, DIMN, p_qkv, nullptr, nullptr, nullptr);

    // 3) K-only l2norm*scale + rotary (in place)
    qkpost_k_kernel<<<NTOK, 256>>>(p_qkv, k_scale, p_rotc, p_rots);

    // 4) attention (fused Q transform) -> fp16
    attn_kernel<<<dim3(NW, HEADS, BATCH), 128>>>(p_qkv, q_scale, p_rotc, p_rots, p_at);

    // 5) x1 = x + attn @ w_out^T + b_out
    gemm_tc<1><<<dim3(DIMN / 128, NTOK / 128), 256, SM_TOTAL>>>(
        p_at, p_wout, NTOK, DIMN, DIMN, p_x1, nullptr, b_out, x);

    // 6) h = LN2(x1) -> fp16
    ln_kernel<<<NTOK, 128>>>(p_x1, ff_ln_g, ff_ln_b, p_h);

    // 7) ff1 = gelu(h @ w_ff1^T) -> fp16
    gemm_tc<2><<<dim3(FFD / 128, NTOK / 128), 256, SM_TOTAL>>>(
        p_h, p_wff1, NTOK, FFD, DIMN, nullptr, p_f1, nullptr, nullptr);

    // 8) out = x1 + ff1 @ w_ff2^T
    gemm_tc<3><<<dim3(DIMN / 128, NTOK / 128), 256, SM_TOTAL>>>(
        p_f1, p_wff2, NTOK, DIMN, FFD, out, nullptr, nullptr, p_x1);
}

// round 16
// speedup vs baseline: 1.0940x; 1.0587x over previous
#include <cuda_runtime.h>
#include <cuda_bf16.h>
#include <cuda_fp16.h>
#include <stdint.h>
#include <math.h>

#define BATCH   8
#define SEQ     4096
#define DIMN    512
#define HEADS   8
#define DHEAD   64
#define WIN     128
#define NW      (SEQ / WIN)
#define NTOK    (BATCH * SEQ)
#define QKVD    (3 * DIMN)
#define FFD     (4 * DIMN)

#define WSCALE     512.0f            // weights pre-scaled by 512 (exact pow2)
#define WSCALE_INV (1.0f / 512.0f)

// ======================= scratch (static device memory) ========================
__device__ float  g_qkv [(size_t)NTOK * QKVD];
__device__ float  g_x1  [(size_t)NTOK * DIMN];
__device__ __half g_h   [(size_t)NTOK * DIMN];
__device__ __half g_at  [(size_t)NTOK * DIMN];
__device__ __half g_f1  [(size_t)NTOK * FFD];
__device__ __half g_wqkv[QKVD * DIMN];
__device__ __half g_wout[DIMN * DIMN];
__device__ __half g_wff1[FFD * DIMN];
__device__ __half g_wff2[DIMN * FFD];
__device__ float  g_rotc[SEQ * 32];   // rotary cos table [pos][pair]
__device__ float  g_rots[SEQ * 32];   // rotary sin table

// ============================ helpers ==========================================
__device__ __forceinline__ uint32_t smem_u32(const void* p) {
    uint32_t a;
    asm("{ .reg .u64 t; cvta.to.shared.u64 t, %1; cvt.u32.u64 %0, t; }" : "=r"(a) : "l"(p));
    return a;
}
#define SWZ(o) ((o) ^ (((o) >> 3) & 0x70))   // SW128 swizzle, 128B rows

__device__ __forceinline__ void cp_async16(uint32_t dst, const void* src) {
    asm volatile("cp.async.cg.shared.global [%0], [%1], 16;" :: "r"(dst), "l"(src));
}
__device__ __forceinline__ void cp_commit() {
    asm volatile("cp.async.commit_group;");
}
template <int N>
__device__ __forceinline__ void cp_wait() {
    asm volatile("cp.async.wait_group %0;" :: "n"(N));
}
__device__ __forceinline__ void ldmatrix_x4(uint32_t& r0, uint32_t& r1,
                                            uint32_t& r2, uint32_t& r3, uint32_t a) {
    asm volatile("ldmatrix.sync.aligned.m8n8.x4.shared.b16 {%0,%1,%2,%3}, [%4];"
                 : "=r"(r0), "=r"(r1), "=r"(r2), "=r"(r3) : "r"(a));
}
__device__ __forceinline__ void mma_fp16(float* c, const uint32_t* a, const uint32_t* b) {
    asm volatile("mma.sync.aligned.m16n8k16.row.col.f32.f16.f16.f32 "
                 "{%0,%1,%2,%3}, {%4,%5,%6,%7}, {%8,%9}, {%0,%1,%2,%3};"
                 : "+f"(c[0]), "+f"(c[1]), "+f"(c[2]), "+f"(c[3])
                 : "r"(a[0]), "r"(a[1]), "r"(a[2]), "r"(a[3]), "r"(b[0]), "r"(b[1]));
}

// ---- packed fp32x2 (Blackwell): 2 IEEE fp32 ops per instruction ----
__device__ __forceinline__ unsigned long long ffma2(unsigned long long a,
                                                    unsigned long long b,
                                                    unsigned long long c) {
    unsigned long long d;
    asm("fma.rn.f32x2 %0, %1, %2, %3;" : "=l"(d) : "l"(a), "l"(b), "l"(c));
    return d;
}
__device__ __forceinline__ unsigned long long addf2(unsigned long long a,
                                                    unsigned long long b) {
    unsigned long long d;
    asm("add.rn.f32x2 %0, %1, %2;" : "=l"(d) : "l"(a), "l"(b));
    return d;
}
__device__ __forceinline__ float2 unpack2(unsigned long long v) {
    float2 r;
    asm("mov.b64 {%0, %1}, %2;" : "=f"(r.x), "=f"(r.y) : "l"(v));
    return r;
}
__device__ __forceinline__ unsigned long long pack2(float x, float y) {
    unsigned long long v;
    asm("mov.b64 %0, {%1, %2};" : "=l"(v) : "f"(x), "f"(y));
    return v;
}

// ================= LayerNorm -> fp16. block = token =============================
__global__ __launch_bounds__(128) void ln_kernel(const float* __restrict__ in,
                                                 const float* __restrict__ gamma,
                                                 const float* __restrict__ beta,
                                                 __half* __restrict__ oh)
{
    int t = blockIdx.x;
    int tid = threadIdx.x;
    const float4* row = (const float4*)(in + (size_t)t * DIMN);
    float4 v = row[tid];
    float s  = v.x + v.y + v.z + v.w;
    float ss = v.x * v.x + v.y * v.y + v.z * v.z + v.w * v.w;
#pragma unroll
    for (int o = 16; o > 0; o >>= 1) {
        s  += __shfl_xor_sync(0xffffffffu, s, o);
        ss += __shfl_xor_sync(0xffffffffu, ss, o);
    }
    __shared__ float sm[4], sm2[4];
    int w = tid >> 5, lane = tid & 31;
    if (lane == 0) { sm[w] = s; sm2[w] = ss; }
    __syncthreads();
    s  = sm[0] + sm[1] + sm[2] + sm[3];
    ss = sm2[0] + sm2[1] + sm2[2] + sm2[3];
    float mean = s * (1.0f / DIMN);
    float var  = ss * (1.0f / DIMN) - mean * mean;
    float inv  = rsqrtf(var + 1e-5f);
    float4 g = ((const float4*)gamma)[tid];
    float4 b = ((const float4*)beta)[tid];
    float o0 = (v.x - mean) * inv * g.x + b.x;
    float o1 = (v.y - mean) * inv * g.y + b.y;
    float o2 = (v.z - mean) * inv * g.z + b.z;
    float o3 = (v.w - mean) * inv * g.w + b.w;
    __half2 p0 = __floats2half2_rn(o0, o1);
    __half2 p1 = __floats2half2_rn(o2, o3);
    *(uint2*)(oh + (size_t)t * DIMN + tid * 4) = make_uint2(*(uint32_t*)&p0, *(uint32_t*)&p1);
}

// ========= weight convert: fp32 -> fp16 of (512 * w) ============================
__global__ void wconv_kernel(const float* __restrict__ in,
                             __half* __restrict__ oh, int n4)
{
    int i = blockIdx.x * blockDim.x + threadIdx.x;
    if (i >= n4) return;
    float4 v = ((const float4*)in)[i];
    __half2 p0 = __floats2half2_rn(v.x * WSCALE, v.y * WSCALE);
    __half2 p1 = __floats2half2_rn(v.z * WSCALE, v.w * WSCALE);
    ((uint2*)oh)[i] = make_uint2(*(uint32_t*)&p0, *(uint32_t*)&p1);
}

// ========= rotary table: cos/sin of fp32 phase, exact double trig ===============
__global__ void rotary_kernel(float* __restrict__ rc, float* __restrict__ rs)
{
    int idx = blockIdx.x * blockDim.x + threadIdx.x;   // SEQ*32
    int n = idx >> 5, lane = idx & 31;
    double invf_d = exp(-(double)(2 * lane) * (9.210340371976184 / 64.0));
    float ph = (float)n * (float)invf_d;               // fp32 phase (matches ref)
    double sd, cd;
    sincos((double)ph, &sd, &cd);
    rc[idx] = (float)cd;
    rs[idx] = (float)sd;
}

// ====== local-window attention (R13 verbatim): f32x2, fixed-offset softmax =====
__global__ __launch_bounds__(128) void attn_kernel(const float* __restrict__ qkv,
                                                   __half* __restrict__ oh)
{
    __shared__ float sK[64][DHEAD];
    __shared__ float sV[64][DHEAD];

    int w = blockIdx.x, h = blockIdx.y, b = blockIdx.z;
    int i = threadIdx.x;
    int tok0 = b * SEQ + w * WIN;
    int tok  = tok0 + i;

    unsigned long long q2[32];   // 64 dims as 32 packed fp32 pairs
    {
        const ulonglong2* srcQ = (const ulonglong2*)(qkv + (size_t)tok * QKVD + h * DHEAD);
#pragma unroll
        for (int d = 0; d < 16; ++d) {
            ulonglong2 t2 = srcQ[d];
            q2[2 * d] = t2.x; q2[2 * d + 1] = t2.y;
        }
    }

    unsigned long long acc2[32];
#pragma unroll
    for (int d = 0; d < 32; ++d) acc2[d] = 0ull;
    float l = 0.f;

#pragma unroll 1
    for (int c = 0; c < 4; ++c) {
        if (c < 2 && w == 0) continue;

        __syncthreads();
        {
            int r  = i >> 1;
            int f0 = (i & 1) * 8;
            int ktok = tok0 + c * 64 - WIN + r;
            const float4* sk = (const float4*)(qkv + (size_t)ktok * QKVD + DIMN + h * DHEAD);
            const float4* sv = (const float4*)(qkv + (size_t)ktok * QKVD + 2 * DIMN + h * DHEAD);
            float4* dK = (float4*)&sK[r][0];
            float4* dV = (float4*)&sV[r][0];
#pragma unroll
            for (int f = 0; f < 8; ++f) { dK[f0 + f] = sk[f0 + f]; dV[f0 + f] = sv[f0 + f]; }
        }
        __syncthreads();

        int jmax;
        if (c < 2) jmax = 64;
        else {
            jmax = i - (c - 2) * 64 + 1;
            jmax = jmax < 0 ? 0 : (jmax > 64 ? 64 : jmax);
        }
        for (int j = 0; j < jmax; ++j) {
            const ulonglong2* kr = (const ulonglong2*)&sK[j][0];
            unsigned long long s0 = 0ull, s1 = 0ull, s2 = 0ull, s3 = 0ull;
#pragma unroll
            for (int d = 0; d < 16; ++d) {
                ulonglong2 kk = kr[d];
                if (d & 1) {
                    s2 = ffma2(q2[2 * d],     kk.x, s2);
                    s3 = ffma2(q2[2 * d + 1], kk.y, s3);
                } else {
                    s0 = ffma2(q2[2 * d],     kk.x, s0);
                    s1 = ffma2(q2[2 * d + 1], kk.y, s1);
                }
            }
            unsigned long long tsum = addf2(addf2(s0, s1), addf2(s2, s3));
            float2 tf = unpack2(tsum);
            float sc = (tf.x + tf.y) * 8.0f;   // QK_SCALE; |sc|<=8 (l2-normed q,k)
            float p  = __expf(sc);             // no overflow; offset-free softmax
            l += p;
            unsigned long long pp = pack2(p, p);
            const ulonglong2* vr = (const ulonglong2*)&sV[j][0];
#pragma unroll
            for (int d = 0; d < 16; ++d) {
                ulonglong2 vv = vr[d];
                acc2[2 * d]     = ffma2(pp, vv.x, acc2[2 * d]);
                acc2[2 * d + 1] = ffma2(pp, vv.y, acc2[2 * d + 1]);
            }
        }
    }

    float invl = 1.0f / l;
    size_t dstoff = (size_t)tok * DIMN + h * DHEAD;
#pragma unroll
    for (int g = 0; g < 8; ++g) {
        uint32_t hp[4];
#pragma unroll
        for (int k = 0; k < 4; ++k) {
            float2 f = unpack2(acc2[g * 4 + k]);
            __half2 hh = __floats2half2_rn(f.x * invl, f.y * invl);
            hp[k] = *(uint32_t*)&hh;
        }
        *(uint4*)(oh + dstoff + g * 8) = make_uint4(hp[0], hp[1], hp[2], hp[3]);
    }
}

// ====== HMMA GEMM fp16, double-buffered cp.async, 2 CTAs/SM ====================
// EPI: 0 fp32 | 1 +bias+resid fp32 | 2 gelu->fp16 | 3 +resid fp32
//      4 qkv epilogue: fused l2norm*scale + rotary for Q/K column regions.
//        A warp's 64-col slab = one head; lanes {4r..4r+3} hold all 64 dims of
//        a token-row (16 cols each); rotary partners (d, d+32) = (ni, ni+4) in
//        the SAME thread. ssq = 8 local squares + shfl_xor(1,2).
#define KBLK     64
#define TILE_B   16384
#define STAGE_B  (2 * TILE_B)
#define SM_TOTAL (2 * STAGE_B)

__device__ __forceinline__ float gelu_f(float x)
{
    return 0.5f * x * (1.0f + erff(x * 0.7071067811865476f));
}

template <int EPI>
__global__ __launch_bounds__(256, 2) void gemm_tc(
    const __half* __restrict__ A, const __half* __restrict__ B,
    int M, int N, int K,
    float* __restrict__ Cf, __half* __restrict__ Ch,
    const float* __restrict__ bias, const float* __restrict__ resid,
    const float* __restrict__ scq, const float* __restrict__ sck,
    const float* __restrict__ rc,  const float* __restrict__ rs)
{
    extern __shared__ char smem[];
    uint32_t sb = smem_u32(smem);
    int tid = threadIdx.x, wid = tid >> 5, lane = tid & 31;
    int warpM = wid & 3, warpN = wid >> 2;
    int bm = blockIdx.y * 128, bn = blockIdx.x * 128;

    float acc[2][8][4];
#pragma unroll
    for (int mi = 0; mi < 2; ++mi)
#pragma unroll
        for (int ni = 0; ni < 8; ++ni)
#pragma unroll
            for (int r = 0; r < 4; ++r) acc[mi][ni][r] = 0.f;

    int aRow  = lane & 15;
    int aKoff = (lane >> 4) << 3;
    int bRow  = (lane & 7) + ((lane >> 4) << 3);
    int bKoff = ((lane >> 3) & 1) << 3;

    int ldRow = tid >> 3, ldC16 = tid & 7;

    int kchunks = K / KBLK;

#pragma unroll
    for (int tile = 0; tile < 2; ++tile) {
        const __half* src = (tile == 0) ? A : B;
        int rbase = (tile == 0) ? bm : bn;
        uint32_t dstb = sb + tile * TILE_B;
#pragma unroll
        for (int it = 0; it < 4; ++it) {
            int row = ldRow + it * 32;
            cp_async16(dstb + SWZ(row * 128 + ldC16 * 16),
                       src + (size_t)(rbase + row) * K + ldC16 * 8);
        }
    }
    cp_commit();

#pragma unroll 1
    for (int kc = 0; kc < kchunks; ++kc) {
        uint32_t cur = sb + (uint32_t)(kc & 1) * STAGE_B;
        if (kc + 1 < kchunks) {
            uint32_t nxt = sb + (uint32_t)((kc + 1) & 1) * STAGE_B;
            int k0 = (kc + 1) * KBLK;
#pragma unroll
            for (int tile = 0; tile < 2; ++tile) {
                const __half* src = (tile == 0) ? A : B;
                int rbase = (tile == 0) ? bm : bn;
                uint32_t dstb = nxt + tile * TILE_B;
#pragma unroll
                for (int it = 0; it < 4; ++it) {
                    int row = ldRow + it * 32;
                    cp_async16(dstb + SWZ(row * 128 + ldC16 * 16),
                               src + (size_t)(rbase + row) * K + k0 + ldC16 * 8);
                }
            }
            cp_commit();
            cp_wait<1>();
        } else {
            cp_wait<0>();
        }
        __syncthreads();

#pragma unroll
        for (int k16 = 0; k16 < KBLK / 16; ++k16) {
            uint32_t aOff  = SWZ((warpM * 32 + aRow) * 128 + (k16 * 16 + aKoff) * 2);
            uint32_t aOff2 = SWZ((warpM * 32 + 16 + aRow) * 128 + (k16 * 16 + aKoff) * 2);
            uint32_t a[2][4], b[8][2];

            ldmatrix_x4(a[0][0], a[0][1], a[0][2], a[0][3], cur + aOff);
            ldmatrix_x4(a[1][0], a[1][1], a[1][2], a[1][3], cur + aOff2);
#pragma unroll
            for (int np = 0; np < 4; ++np) {
                uint32_t bo = SWZ((warpN * 64 + np * 16 + bRow) * 128 +
                                  (k16 * 16 + bKoff) * 2);
                ldmatrix_x4(b[np * 2][0], b[np * 2][1],
                            b[np * 2 + 1][0], b[np * 2 + 1][1], cur + TILE_B + bo);
            }
#pragma unroll
            for (int mi = 0; mi < 2; ++mi)
#pragma unroll
                for (int ni = 0; ni < 8; ++ni)
                    mma_fp16(acc[mi][ni], a[mi], b[ni]);
        }
        __syncthreads();
    }

    if (EPI == 4) {
        // whole 128-col tile is inside one 512-aligned region (Q, K, or V)
        const float* sc = (bn < DIMN) ? scq : (bn < 2 * DIMN ? sck : nullptr);
#pragma unroll
        for (int mi = 0; mi < 2; ++mi)
#pragma unroll
            for (int hh = 0; hh < 2; ++hh) {
                int r = bm + warpM * 32 + mi * 16 + (lane >> 2) + hh * 8;
                float v0[8], v1[8];
#pragma unroll
                for (int ni = 0; ni < 8; ++ni) {
                    v0[ni] = acc[mi][ni][hh * 2 + 0] * WSCALE_INV;
                    v1[ni] = acc[mi][ni][hh * 2 + 1] * WSCALE_INV;
                }
                if (sc) {   // uniform per CTA
                    float ssq = 0.f;
#pragma unroll
                    for (int ni = 0; ni < 8; ++ni)
                        ssq += v0[ni] * v0[ni] + v1[ni] * v1[ni];
                    ssq += __shfl_xor_sync(0xffffffffu, ssq, 1);
                    ssq += __shfl_xor_sync(0xffffffffu, ssq, 2);
                    float inv = 1.0f / fmaxf(sqrtf(ssq), 1e-12f);
                    int n = r & (SEQ - 1);
                    int off = (lane & 3) * 2;
#pragma unroll
                    for (int ni = 0; ni < 4; ++ni) {
                        int d = ni * 8 + off;                 // d in [0,31)
                        float c0 = rc[n * 32 + d],     s0 = rs[n * 32 + d];
                        float c1 = rc[n * 32 + d + 1], s1 = rs[n * 32 + d + 1];
                        float lo0 = v0[ni]     * inv * sc[d];
                        float hi0 = v0[ni + 4] * inv * sc[d + 32];
                        float lo1 = v1[ni]     * inv * sc[d + 1];
                        float hi1 = v1[ni + 4] * inv * sc[d + 33];
                        v0[ni]     = lo0 * c0 - hi0 * s0;
                        v0[ni + 4] = hi0 * c0 + lo0 * s0;
                        v1[ni]     = lo1 * c1 - hi1 * s1;
                        v1[ni + 4] = hi1 * c1 + lo1 * s1;
                    }
                }
#pragma unroll
                for (int ni = 0; ni < 8; ++ni) {
                    int col = bn + warpN * 64 + ni * 8 + (lane & 3) * 2;
                    *(float2*)(Cf + (size_t)r * N + col) = make_float2(v0[ni], v1[ni]);
                }
            }
        return;
    }

#pragma unroll
    for (int mi = 0; mi < 2; ++mi)
#pragma unroll
        for (int ni = 0; ni < 8; ++ni) {
            int row = bm + warpM * 32 + mi * 16 + (lane >> 2);
            int col = bn + warpN * 64 + ni * 8 + (lane & 3) * 2;
#pragma unroll
            for (int hh = 0; hh < 2; ++hh) {
                int r = row + hh * 8;
                float v0 = acc[mi][ni][hh * 2 + 0] * WSCALE_INV;
                float v1 = acc[mi][ni][hh * 2 + 1] * WSCALE_INV;
                size_t idx = (size_t)r * N + col;
                if (EPI == 2) {
                    __half2 hp = __floats2half2_rn(gelu_f(v0), gelu_f(v1));
                    *(uint32_t*)(Ch + idx) = *(uint32_t*)&hp;
                } else {
                    if (EPI == 1) {
                        float2 rs2 = *(const float2*)(resid + idx);
                        v0 += bias[col] + rs2.x;
                        v1 += bias[col + 1] + rs2.y;
                    } else if (EPI == 3) {
                        float2 rs2 = *(const float2*)(resid + idx);
                        v0 += rs2.x; v1 += rs2.y;
                    }
                    *(float2*)(Cf + idx) = make_float2(v0, v1);
                }
            }
        }
}

// ------------------------------- launch ---------------------------------------
extern "C" void kernel_launch(void* const* d_in, const int* in_sizes, int n_in,
                              void* d_out, int out_size)
{
    const float* x       = (const float*)d_in[0];
    const float* w_qkv   = (const float*)d_in[1];
    const float* q_scale = (const float*)d_in[2];
    const float* k_scale = (const float*)d_in[3];
    const float* w_out   = (const float*)d_in[4];
    const float* b_out   = (const float*)d_in[5];
    const float* ln1_g   = (const float*)d_in[6];
    const float* ln1_b   = (const float*)d_in[7];
    const float* ff_ln_g = (const float*)d_in[8];
    const float* ff_ln_b = (const float*)d_in[9];
    const float* w_ff1   = (const float*)d_in[10];
    const float* w_ff2   = (const float*)d_in[11];
    float* out = (float*)d_out;

    float *p_qkv, *p_x1, *p_rotc, *p_rots;
    __half *p_h, *p_at, *p_f1, *p_wqkv, *p_wout, *p_wff1, *p_wff2;
    cudaGetSymbolAddress((void**)&p_qkv, g_qkv);
    cudaGetSymbolAddress((void**)&p_x1, g_x1);
    cudaGetSymbolAddress((void**)&p_rotc, g_rotc);
    cudaGetSymbolAddress((void**)&p_rots, g_rots);
    cudaGetSymbolAddress((void**)&p_h, g_h);
    cudaGetSymbolAddress((void**)&p_at, g_at);
    cudaGetSymbolAddress((void**)&p_f1, g_f1);
    cudaGetSymbolAddress((void**)&p_wqkv, g_wqkv);
    cudaGetSymbolAddress((void**)&p_wout, g_wout);
    cudaGetSymbolAddress((void**)&p_wff1, g_wff1);
    cudaGetSymbolAddress((void**)&p_wff2, g_wff2);

    cudaFuncSetAttribute(gemm_tc<1>, cudaFuncAttributeMaxDynamicSharedMemorySize, SM_TOTAL);
    cudaFuncSetAttribute(gemm_tc<2>, cudaFuncAttributeMaxDynamicSharedMemorySize, SM_TOTAL);
    cudaFuncSetAttribute(gemm_tc<3>, cudaFuncAttributeMaxDynamicSharedMemorySize, SM_TOTAL);
    cudaFuncSetAttribute(gemm_tc<4>, cudaFuncAttributeMaxDynamicSharedMemorySize, SM_TOTAL);

    // rotary table + weight converts
    rotary_kernel<<<(SEQ * 32) / 256, 256>>>(p_rotc, p_rots);
    wconv_kernel<<<(QKVD * DIMN / 4 + 255) / 256, 256>>>(w_qkv, p_wqkv, QKVD * DIMN / 4);
    wconv_kernel<<<(DIMN * DIMN / 4 + 255) / 256, 256>>>(w_out, p_wout, DIMN * DIMN / 4);
    wconv_kernel<<<(FFD * DIMN / 4 + 255) / 256, 256>>>(w_ff1, p_wff1, FFD * DIMN / 4);
    wconv_kernel<<<(DIMN * FFD / 4 + 255) / 256, 256>>>(w_ff2, p_wff2, DIMN * FFD / 4);

    // 1) h = LN1(x) -> fp16
    ln_kernel<<<NTOK, 128>>>(x, ln1_g, ln1_b, p_h);

    // 2) qkv = h @ w_qkv^T with FUSED q/k l2norm*scale+rotary in the epilogue
    gemm_tc<4><<<dim3(QKVD / 128, NTOK / 128), 256, SM_TOTAL>>>(
        p_h, p_wqkv, NTOK, QKVD, DIMN, p_qkv, nullptr, nullptr, nullptr,
        q_scale, k_scale, p_rotc, p_rots);

    // 3) attention -> fp16 (R13 kernel, q/k already transformed)
    attn_kernel<<<dim3(NW, HEADS, BATCH), 128>>>(p_qkv, p_at);

    // 4) x1 = x + attn @ w_out^T + b_out
    gemm_tc<1><<<dim3(DIMN / 128, NTOK / 128), 256, SM_TOTAL>>>(
        p_at, p_wout, NTOK, DIMN, DIMN, p_x1, nullptr, b_out, x,
        nullptr, nullptr, nullptr, nullptr);

    // 5) h = LN2(x1) -> fp16
    ln_kernel<<<NTOK, 128>>>(p_x1, ff_ln_g, ff_ln_b, p_h);

    // 6) ff1 = gelu(h @ w_ff1^T) -> fp16
    gemm_tc<2><<<dim3(FFD / 128, NTOK / 128), 256, SM_TOTAL>>>(
        p_h, p_wff1, NTOK, FFD, DIMN, nullptr, p_f1, nullptr, nullptr,
        nullptr, nullptr, nullptr, nullptr);

    // 7) out = x1 + ff1 @ w_ff2^T
    gemm_tc<3><<<dim3(DIMN / 128, NTOK / 128), 256, SM_TOTAL>>>(
        p_f1, p_wff2, NTOK, DIMN, FFD, out, nullptr, nullptr, p_x1,
        nullptr, nullptr, nullptr, nullptr);
}